// round 10
// baseline (speedup 1.0000x reference)
#include <cuda_runtime.h>

#define BATCH 262144
#define SDIM  100
#define HID   256
#define ENC   128
#define EXPH  64
#define ACTD  10
#define NK    10
#define GRID1 2048          // BATCH/128

typedef unsigned long long u64;

// ---- device-global scratch (no allocation allowed) ----
__device__ float g_h[BATCH * HID];
__device__ float g_enc[BATCH * ENC];
__device__ float g_psum[GRID1 * HID];
__device__ float g_psq [GRID1 * HID];
__device__ float g_scale[HID];
__device__ float g_shift[HID];

// ---- packed fp32x2 helpers (FFMA2 only reachable via PTX) ----
__device__ __forceinline__ u64 dupf(float w) {
    u64 d; asm("mov.b64 %0, {%1, %1};" : "=l"(d) : "f"(w)); return d;
}
__device__ __forceinline__ void fma2(u64 &a, u64 x, u64 y) {
    asm("fma.rn.f32x2 %0, %1, %2, %0;" : "+l"(a) : "l"(x), "l"(y));
}
__device__ __forceinline__ float2 unp(u64 v) {
    float2 r; asm("mov.b64 {%0, %1}, %2;" : "=f"(r.x), "=f"(r.y) : "l"(v)); return r;
}
__device__ __forceinline__ float ftanh(float x) {
    float v = fminf(fmaxf(x, -15.f), 15.f);
    float t = __expf(2.f * v);
    return __fdividef(t - 1.f, t + 1.f);
}

// =====================================================================
// K1: h = relu(state @ W1 + b1) + per-block column sum/sumsq
// grid (2048,2) x 256 thr. smem: st pairs [100][65]u64 | W1 [100][128] | b1
// =====================================================================
#define K1_SMEM (100*65*8 + 100*128*4 + 128*4)   // 52000+51200+512 = 103712

__global__ void __launch_bounds__(256) k1_gemm_relu(
    const float* __restrict__ state, const float* __restrict__ W1,
    const float* __restrict__ b1)
{
    extern __shared__ char sm[];
    float* stf = (float*)sm;                 // float view: k*130 + r
    u64*   st2 = (u64*)sm;                   // pair view:  k*65 + rp
    float* w1s = (float*)(sm + 52000);       // [100][128]
    float* b1s = (float*)(sm + 103200);

    const int tid  = threadIdx.x;
    const int row0 = blockIdx.x * 128;
    const int cb   = blockIdx.y;

    for (int idx = tid; idx < 128 * SDIM; idx += 256) {
        int r = idx / SDIM, k = idx - r * SDIM;
        stf[k * 130 + r] = state[(size_t)(row0 + r) * SDIM + k];
    }
    for (int idx = tid; idx < SDIM * 128; idx += 256) {
        int k = idx >> 7, c = idx & 127;
        w1s[idx] = W1[k * HID + cb * 128 + c];
    }
    if (tid < 128) b1s[tid] = b1[cb * 128 + tid];
    __syncthreads();

    const int tc = tid & 15, tr = tid >> 4;
    u64 acc[4][8];
    #pragma unroll
    for (int j = 0; j < 4; ++j)
        #pragma unroll
        for (int u = 0; u < 8; ++u) acc[j][u] = 0ull;

    #pragma unroll 2
    for (int k = 0; k < SDIM; ++k) {
        u64 p0 = st2[k * 65 + tr * 4 + 0];
        u64 p1 = st2[k * 65 + tr * 4 + 1];
        u64 p2 = st2[k * 65 + tr * 4 + 2];
        u64 p3 = st2[k * 65 + tr * 4 + 3];
        float4 wa = *(const float4*)(w1s + k * 128 + tc * 8);
        float4 wb = *(const float4*)(w1s + k * 128 + tc * 8 + 4);
        float wv[8] = {wa.x, wa.y, wa.z, wa.w, wb.x, wb.y, wb.z, wb.w};
        #pragma unroll
        for (int u = 0; u < 8; ++u) {
            u64 d = dupf(wv[u]);
            fma2(acc[0][u], p0, d); fma2(acc[1][u], p1, d);
            fma2(acc[2][u], p2, d); fma2(acc[3][u], p3, d);
        }
    }

    float csum[8], csq[8], bvals[8];
    #pragma unroll
    for (int u = 0; u < 8; ++u) { csum[u] = 0.f; csq[u] = 0.f; bvals[u] = b1s[tc * 8 + u]; }

    #pragma unroll
    for (int j = 0; j < 4; ++j) {
        float v0[8], v1[8];
        #pragma unroll
        for (int u = 0; u < 8; ++u) {
            float2 t = unp(acc[j][u]);
            float x0 = fmaxf(t.x + bvals[u], 0.f);
            float x1 = fmaxf(t.y + bvals[u], 0.f);
            v0[u] = x0; v1[u] = x1;
            csum[u] += x0 + x1;
            csq[u]  += x0 * x0 + x1 * x1;
        }
        int rg = row0 + tr * 8 + 2 * j;
        float* hp = g_h + (size_t)rg * HID + cb * 128 + tc * 8;
        *(float4*)hp       = make_float4(v0[0], v0[1], v0[2], v0[3]);
        *(float4*)(hp + 4) = make_float4(v0[4], v0[5], v0[6], v0[7]);
        hp += HID;
        *(float4*)hp       = make_float4(v1[0], v1[1], v1[2], v1[3]);
        *(float4*)(hp + 4) = make_float4(v1[4], v1[5], v1[6], v1[7]);
    }

    __syncthreads();
    float* red = (float*)sm;                 // alias, [16][128]
    #pragma unroll
    for (int u = 0; u < 8; ++u) red[tr * 128 + tc * 8 + u] = csum[u];
    __syncthreads();
    if (tid < 128) {
        float s = 0.f;
        #pragma unroll
        for (int q = 0; q < 16; ++q) s += red[q * 128 + tid];
        g_psum[blockIdx.x * HID + cb * 128 + tid] = s;
    }
    __syncthreads();
    #pragma unroll
    for (int u = 0; u < 8; ++u) red[tr * 128 + tc * 8 + u] = csq[u];
    __syncthreads();
    if (tid < 128) {
        float s = 0.f;
        #pragma unroll
        for (int q = 0; q < 16; ++q) s += red[q * 128 + tid];
        g_psq[blockIdx.x * HID + cb * 128 + tid] = s;
    }
}

// =====================================================================
// K2: finalize BN stats -> scale/shift
// =====================================================================
__global__ void k2_bnstats(const float* __restrict__ gamma,
                           const float* __restrict__ beta)
{
    __shared__ float rs[256], rq[256];
    const int c = blockIdx.x, tid = threadIdx.x;
    float s = 0.f, q = 0.f;
    for (int i = tid; i < GRID1; i += 256) {
        s += g_psum[i * HID + c];
        q += g_psq [i * HID + c];
    }
    rs[tid] = s; rq[tid] = q;
    __syncthreads();
    for (int off = 128; off > 0; off >>= 1) {
        if (tid < off) { rs[tid] += rs[tid + off]; rq[tid] += rq[tid + off]; }
        __syncthreads();
    }
    if (tid == 0) {
        const float invB = 1.f / (float)BATCH;
        float mu  = rs[0] * invB;
        float var = fmaxf(rq[0] * invB - mu * mu, 0.f);
        float sc  = gamma[c] * rsqrtf(var + 1e-5f);
        g_scale[c] = sc;
        g_shift[c] = beta[c] - mu * sc;
    }
}

// =====================================================================
// K3: enc = tanh( BN(h) @ W2 + b2 ). 128x128 tile, K=256 in chunks of 64.
// smem: A pairs [64][65]u64 | W2 chunk [64][128] | scale/shift/b2
// =====================================================================
#define K3_SMEM (64*65*8 + 64*128*4 + 256*4*2 + 128*4)  // 33280+32768+2048+512

__global__ void __launch_bounds__(256) k3_gemm_tanh(
    const float* __restrict__ W2, const float* __restrict__ b2)
{
    extern __shared__ char sm[];
    u64*   hA2 = (u64*)sm;                   // [kk][65]
    float* hAf = (float*)sm;                 // kk*130 + r
    float* wB  = (float*)(sm + 33280);       // [64][128]
    float* ssc = (float*)(sm + 66048);
    float* ssh = ssc + 256;
    float* sb2 = ssh + 256;

    const int tid  = threadIdx.x;
    const int row0 = blockIdx.x * 128;
    ssc[tid] = g_scale[tid];
    ssh[tid] = g_shift[tid];
    if (tid < 128) sb2[tid] = b2[tid];

    const int tc = tid & 15, tr = tid >> 4;
    u64 acc[4][8];
    #pragma unroll
    for (int j = 0; j < 4; ++j)
        #pragma unroll
        for (int u = 0; u < 8; ++u) acc[j][u] = 0ull;

    for (int kc = 0; kc < HID; kc += 64) {
        __syncthreads();
        for (int idx = tid; idx < 128 * 64; idx += 256) {
            int r = idx >> 6, kk = idx & 63;
            float v = g_h[(size_t)(row0 + r) * HID + kc + kk];
            hAf[kk * 130 + r] = v * ssc[kc + kk] + ssh[kc + kk];
        }
        for (int idx = tid; idx < 64 * 128; idx += 256)
            wB[idx] = W2[(size_t)(kc + (idx >> 7)) * ENC + (idx & 127)];
        __syncthreads();

        #pragma unroll 2
        for (int kk = 0; kk < 64; ++kk) {
            u64 p0 = hA2[kk * 65 + tr * 4 + 0];
            u64 p1 = hA2[kk * 65 + tr * 4 + 1];
            u64 p2 = hA2[kk * 65 + tr * 4 + 2];
            u64 p3 = hA2[kk * 65 + tr * 4 + 3];
            float4 wa = *(const float4*)(wB + kk * 128 + tc * 8);
            float4 wb = *(const float4*)(wB + kk * 128 + tc * 8 + 4);
            float wv[8] = {wa.x, wa.y, wa.z, wa.w, wb.x, wb.y, wb.z, wb.w};
            #pragma unroll
            for (int u = 0; u < 8; ++u) {
                u64 d = dupf(wv[u]);
                fma2(acc[0][u], p0, d); fma2(acc[1][u], p1, d);
                fma2(acc[2][u], p2, d); fma2(acc[3][u], p3, d);
            }
        }
    }

    #pragma unroll
    for (int j = 0; j < 4; ++j) {
        float v0[8], v1[8];
        #pragma unroll
        for (int u = 0; u < 8; ++u) {
            float2 t = unp(acc[j][u]);
            float bb = sb2[tc * 8 + u];
            v0[u] = ftanh(t.x + bb);
            v1[u] = ftanh(t.y + bb);
        }
        int rg = row0 + tr * 8 + 2 * j;
        float* ep = g_enc + (size_t)rg * ENC + tc * 8;
        *(float4*)ep       = make_float4(v0[0], v0[1], v0[2], v0[3]);
        *(float4*)(ep + 4) = make_float4(v0[4], v0[5], v0[6], v0[7]);
        ep += ENC;
        *(float4*)ep       = make_float4(v1[0], v1[1], v1[2], v1[3]);
        *(float4*)(ep + 4) = make_float4(v1[4], v1[5], v1[6], v1[7]);
    }
}

// =====================================================================
// K4: fused distance->softmax + 10 experts + weighted output.
// smem: enc pairs [128e][65rp]u64 | eh [128][69] | We1 [128][64] |
//       We2 padded [64][12] | att [10][128] | be1/be2/attn
// =====================================================================
#define K4_SMEM (128*65*8 + 128*69*4 + 128*64*4 + (768+1280+64+16+16)*4)

__global__ void __launch_bounds__(256) k4_fused(
    const float* __restrict__ We1, const float* __restrict__ be1,
    const float* __restrict__ We2, const float* __restrict__ be2,
    const float* __restrict__ attr, float* __restrict__ out)
{
    extern __shared__ char sm[];
    u64*   enc2 = (u64*)sm;                  // e*65 + rp
    float* encf = (float*)sm;                // e*130 + r
    float* ehs  = (float*)(sm + 66560);      // [128][69]
    float* we1s = (float*)(sm + 101888);     // [128][64]
    float* we2s = (float*)(sm + 134656);     // [64][12] padded
    float* att  = we2s + 768;                // [10][128]
    float* be1s = att + 1280;                // 64
    float* be2s = be1s + 64;                 // 16
    float* attn = be2s + 16;                 // 16

    const int tid  = threadIdx.x;
    const int row0 = blockIdx.x * 128;

    for (int idx = tid; idx < 128 * 128; idx += 256) {
        int r = idx >> 7, e = idx & 127;
        encf[e * 130 + r] = g_enc[(size_t)(row0 + r) * ENC + e];
    }
    for (int idx = tid; idx < NK * ENC; idx += 256) att[idx] = attr[idx];
    __syncthreads();
    if (tid < NK) {
        float s = 0.f;
        for (int e = 0; e < ENC; ++e) { float v = att[tid * ENC + e]; s += v * v; }
        attn[tid] = s;
    }
    __syncthreads();

    // distances + softmax -> strengths in registers (threads 0..127 own a row)
    float strk[NK];
    float outacc[ACTD];
    #pragma unroll
    for (int a = 0; a < ACTD; ++a) outacc[a] = 0.f;

    if (tid < 128) {
        float en = 0.f;
        for (int e = 0; e < ENC; ++e) { float v = encf[e * 130 + tid]; en += v * v; }
        float mx = -1e30f;
        #pragma unroll
        for (int k = 0; k < NK; ++k) {
            float d = 0.f;
            for (int e = 0; e < ENC; ++e) d += encf[e * 130 + tid] * att[k * ENC + e];
            float d2 = fmaxf(en + attn[k] - 2.f * d, 0.f);
            strk[k] = -2.f * sqrtf(d2);          // -dist/TEMP, TEMP=0.5
            mx = fmaxf(mx, strk[k]);
        }
        float s = 0.f;
        #pragma unroll
        for (int k = 0; k < NK; ++k) { strk[k] = __expf(strk[k] - mx); s += strk[k]; }
        float inv = __fdividef(1.f, s);
        #pragma unroll
        for (int k = 0; k < NK; ++k) strk[k] *= inv;
    }

    const int tc = tid & 15, trr = tid >> 4;
    for (int k = 0; k < NK; ++k) {
        __syncthreads();
        for (int idx = tid; idx < ENC * EXPH; idx += 256)
            we1s[idx] = We1[(size_t)k * ENC * EXPH + idx];
        for (int idx = tid; idx < EXPH * ACTD; idx += 256)
            we2s[(idx / ACTD) * 12 + (idx % ACTD)] = We2[k * EXPH * ACTD + idx];
        if (tid < EXPH) be1s[tid] = be1[k * EXPH + tid];
        if (tid < ACTD) be2s[tid] = be2[k * ACTD + tid];
        __syncthreads();

        // phase A: eh = relu(enc @ We1_k + be1_k), 8 rows x 4 cols / thread
        u64 acc[4][4];
        #pragma unroll
        for (int j = 0; j < 4; ++j)
            #pragma unroll
            for (int u = 0; u < 4; ++u) acc[j][u] = 0ull;

        #pragma unroll 2
        for (int e = 0; e < ENC; ++e) {
            u64 p0 = enc2[e * 65 + trr * 4 + 0];
            u64 p1 = enc2[e * 65 + trr * 4 + 1];
            u64 p2 = enc2[e * 65 + trr * 4 + 2];
            u64 p3 = enc2[e * 65 + trr * 4 + 3];
            float4 w = *(const float4*)(we1s + e * 64 + tc * 4);
            float wv[4] = {w.x, w.y, w.z, w.w};
            #pragma unroll
            for (int u = 0; u < 4; ++u) {
                u64 d = dupf(wv[u]);
                fma2(acc[0][u], p0, d); fma2(acc[1][u], p1, d);
                fma2(acc[2][u], p2, d); fma2(acc[3][u], p3, d);
            }
        }
        #pragma unroll
        for (int j = 0; j < 4; ++j) {
            int r = trr * 8 + 2 * j;
            #pragma unroll
            for (int u = 0; u < 4; ++u) {
                float2 t = unp(acc[j][u]);
                float bb = be1s[tc * 4 + u];
                ehs[r * 69 + tc * 4 + u]       = fmaxf(t.x + bb, 0.f);
                ehs[(r + 1) * 69 + tc * 4 + u] = fmaxf(t.y + bb, 0.f);
            }
        }
        __syncthreads();

        // phase B: out += s_k * (eh @ We2_k + be2_k), threads 0..127 own rows
        if (tid < 128) {
            float o[ACTD];
            #pragma unroll
            for (int a = 0; a < ACTD; ++a) o[a] = 0.f;
            #pragma unroll 4
            for (int h = 0; h < EXPH; ++h) {
                float ev = ehs[tid * 69 + h];
                float4 wa = *(const float4*)(we2s + h * 12);
                float4 wb = *(const float4*)(we2s + h * 12 + 4);
                float4 wc = *(const float4*)(we2s + h * 12 + 8);
                o[0] += ev * wa.x; o[1] += ev * wa.y; o[2] += ev * wa.z; o[3] += ev * wa.w;
                o[4] += ev * wb.x; o[5] += ev * wb.y; o[6] += ev * wb.z; o[7] += ev * wb.w;
                o[8] += ev * wc.x; o[9] += ev * wc.y;
            }
            float s = strk[k];
            #pragma unroll
            for (int a = 0; a < ACTD; ++a) outacc[a] += s * (o[a] + be2s[a]);
        }
    }

    if (tid < 128) {
        float* op = out + (size_t)(row0 + tid) * ACTD;
        #pragma unroll
        for (int a = 0; a < ACTD; ++a) op[a] = outacc[a];
    }
}

// =====================================================================
extern "C" void kernel_launch(void* const* d_in, const int* in_sizes, int n_in,
                              void* d_out, int out_size)
{
    const float* state = (const float*)d_in[0];
    const float* W1    = (const float*)d_in[1];
    const float* b1    = (const float*)d_in[2];
    const float* gamma = (const float*)d_in[3];
    const float* beta  = (const float*)d_in[4];
    const float* W2    = (const float*)d_in[5];
    const float* b2    = (const float*)d_in[6];
    const float* We1   = (const float*)d_in[7];
    const float* be1   = (const float*)d_in[8];
    const float* We2   = (const float*)d_in[9];
    const float* be2   = (const float*)d_in[10];
    const float* attr  = (const float*)d_in[11];
    float* out = (float*)d_out;

    cudaFuncSetAttribute(k1_gemm_relu, cudaFuncAttributeMaxDynamicSharedMemorySize, K1_SMEM);
    cudaFuncSetAttribute(k3_gemm_tanh, cudaFuncAttributeMaxDynamicSharedMemorySize, K3_SMEM);
    cudaFuncSetAttribute(k4_fused,     cudaFuncAttributeMaxDynamicSharedMemorySize, K4_SMEM);

    k1_gemm_relu<<<dim3(GRID1, 2), 256, K1_SMEM>>>(state, W1, b1);
    k2_bnstats<<<HID, 256>>>(gamma, beta);
    k3_gemm_tanh<<<GRID1, 256, K3_SMEM>>>(W2, b2);
    k4_fused<<<GRID1, 256, K4_SMEM>>>(We1, be1, We2, be2, attr, out);
}

// round 11
// speedup vs baseline: 1.0011x; 1.0011x over previous
#include <cuda_runtime.h>

#define BATCH 262144
#define SDIM  100
#define HID   256
#define ENC   128
#define EXPH  64
#define ACTD  10
#define NK    10
#define GRID1 2048          // BATCH/128

typedef unsigned long long u64;

// ---- device-global scratch (no allocation allowed) ----
__device__ float g_h[BATCH * HID];
__device__ float g_enc[BATCH * ENC];
__device__ float g_psum[GRID1 * HID];
__device__ float g_psq [GRID1 * HID];
__device__ float g_scale[HID];
__device__ float g_shift[HID];

// ---- packed fp32x2 helpers (FFMA2 only reachable via PTX) ----
__device__ __forceinline__ u64 dupf(float w) {
    u64 d; asm("mov.b64 %0, {%1, %1};" : "=l"(d) : "f"(w)); return d;
}
__device__ __forceinline__ void fma2(u64 &a, u64 x, u64 y) {
    asm("fma.rn.f32x2 %0, %1, %2, %0;" : "+l"(a) : "l"(x), "l"(y));
}
__device__ __forceinline__ float2 unp(u64 v) {
    float2 r; asm("mov.b64 {%0, %1}, %2;" : "=f"(r.x), "=f"(r.y) : "l"(v)); return r;
}
__device__ __forceinline__ float ftanh(float x) {
    float v = fminf(fmaxf(x, -15.f), 15.f);
    float t = __expf(2.f * v);
    return __fdividef(t - 1.f, t + 1.f);
}

// =====================================================================
// K1: h = relu(state @ W1 + b1) + per-block column sum/sumsq
// grid (2048,2) x 256 thr. smem: st pairs [100][65]u64 | W1 [100][128] | b1
// =====================================================================
#define K1_SMEM (100*65*8 + 100*128*4 + 128*4)   // 52000+51200+512 = 103712

__global__ void __launch_bounds__(256) k1_gemm_relu(
    const float* __restrict__ state, const float* __restrict__ W1,
    const float* __restrict__ b1)
{
    extern __shared__ char sm[];
    float* stf = (float*)sm;                 // float view: k*130 + r
    u64*   st2 = (u64*)sm;                   // pair view:  k*65 + rp
    float* w1s = (float*)(sm + 52000);       // [100][128]
    float* b1s = (float*)(sm + 103200);

    const int tid  = threadIdx.x;
    const int row0 = blockIdx.x * 128;
    const int cb   = blockIdx.y;

    for (int idx = tid; idx < 128 * SDIM; idx += 256) {
        int r = idx / SDIM, k = idx - r * SDIM;
        stf[k * 130 + r] = state[(size_t)(row0 + r) * SDIM + k];
    }
    for (int idx = tid; idx < SDIM * 128; idx += 256) {
        int k = idx >> 7, c = idx & 127;
        w1s[idx] = W1[k * HID + cb * 128 + c];
    }
    if (tid < 128) b1s[tid] = b1[cb * 128 + tid];
    __syncthreads();

    const int tc = tid & 15, tr = tid >> 4;
    u64 acc[4][8];
    #pragma unroll
    for (int j = 0; j < 4; ++j)
        #pragma unroll
        for (int u = 0; u < 8; ++u) acc[j][u] = 0ull;

    #pragma unroll 2
    for (int k = 0; k < SDIM; ++k) {
        u64 p0 = st2[k * 65 + tr * 4 + 0];
        u64 p1 = st2[k * 65 + tr * 4 + 1];
        u64 p2 = st2[k * 65 + tr * 4 + 2];
        u64 p3 = st2[k * 65 + tr * 4 + 3];
        float4 wa = *(const float4*)(w1s + k * 128 + tc * 8);
        float4 wb = *(const float4*)(w1s + k * 128 + tc * 8 + 4);
        float wv[8] = {wa.x, wa.y, wa.z, wa.w, wb.x, wb.y, wb.z, wb.w};
        #pragma unroll
        for (int u = 0; u < 8; ++u) {
            u64 d = dupf(wv[u]);
            fma2(acc[0][u], p0, d); fma2(acc[1][u], p1, d);
            fma2(acc[2][u], p2, d); fma2(acc[3][u], p3, d);
        }
    }

    float csum[8], csq[8], bvals[8];
    #pragma unroll
    for (int u = 0; u < 8; ++u) { csum[u] = 0.f; csq[u] = 0.f; bvals[u] = b1s[tc * 8 + u]; }

    #pragma unroll
    for (int j = 0; j < 4; ++j) {
        float v0[8], v1[8];
        #pragma unroll
        for (int u = 0; u < 8; ++u) {
            float2 t = unp(acc[j][u]);
            float x0 = fmaxf(t.x + bvals[u], 0.f);
            float x1 = fmaxf(t.y + bvals[u], 0.f);
            v0[u] = x0; v1[u] = x1;
            csum[u] += x0 + x1;
            csq[u]  += x0 * x0 + x1 * x1;
        }
        int rg = row0 + tr * 8 + 2 * j;
        float* hp = g_h + (size_t)rg * HID + cb * 128 + tc * 8;
        *(float4*)hp       = make_float4(v0[0], v0[1], v0[2], v0[3]);
        *(float4*)(hp + 4) = make_float4(v0[4], v0[5], v0[6], v0[7]);
        hp += HID;
        *(float4*)hp       = make_float4(v1[0], v1[1], v1[2], v1[3]);
        *(float4*)(hp + 4) = make_float4(v1[4], v1[5], v1[6], v1[7]);
    }

    __syncthreads();
    float* red = (float*)sm;                 // alias, [16][128]
    #pragma unroll
    for (int u = 0; u < 8; ++u) red[tr * 128 + tc * 8 + u] = csum[u];
    __syncthreads();
    if (tid < 128) {
        float s = 0.f;
        #pragma unroll
        for (int q = 0; q < 16; ++q) s += red[q * 128 + tid];
        g_psum[blockIdx.x * HID + cb * 128 + tid] = s;
    }
    __syncthreads();
    #pragma unroll
    for (int u = 0; u < 8; ++u) red[tr * 128 + tc * 8 + u] = csq[u];
    __syncthreads();
    if (tid < 128) {
        float s = 0.f;
        #pragma unroll
        for (int q = 0; q < 16; ++q) s += red[q * 128 + tid];
        g_psq[blockIdx.x * HID + cb * 128 + tid] = s;
    }
}

// =====================================================================
// K2: finalize BN stats -> scale/shift
// =====================================================================
__global__ void k2_bnstats(const float* __restrict__ gamma,
                           const float* __restrict__ beta)
{
    __shared__ float rs[256], rq[256];
    const int c = blockIdx.x, tid = threadIdx.x;
    float s = 0.f, q = 0.f;
    for (int i = tid; i < GRID1; i += 256) {
        s += g_psum[i * HID + c];
        q += g_psq [i * HID + c];
    }
    rs[tid] = s; rq[tid] = q;
    __syncthreads();
    for (int off = 128; off > 0; off >>= 1) {
        if (tid < off) { rs[tid] += rs[tid + off]; rq[tid] += rq[tid + off]; }
        __syncthreads();
    }
    if (tid == 0) {
        const float invB = 1.f / (float)BATCH;
        float mu  = rs[0] * invB;
        float var = fmaxf(rq[0] * invB - mu * mu, 0.f);
        float sc  = gamma[c] * rsqrtf(var + 1e-5f);
        g_scale[c] = sc;
        g_shift[c] = beta[c] - mu * sc;
    }
}

// =====================================================================
// K3: enc = tanh( BN(h) @ W2 + b2 ). 128x128 tile, K=256 in chunks of 64.
// smem: A pairs [64][65]u64 | W2 chunk [64][128] | scale/shift/b2
// =====================================================================
#define K3_SMEM (64*65*8 + 64*128*4 + 256*4*2 + 128*4)  // 33280+32768+2048+512

__global__ void __launch_bounds__(256) k3_gemm_tanh(
    const float* __restrict__ W2, const float* __restrict__ b2)
{
    extern __shared__ char sm[];
    u64*   hA2 = (u64*)sm;                   // [kk][65]
    float* hAf = (float*)sm;                 // kk*130 + r
    float* wB  = (float*)(sm + 33280);       // [64][128]
    float* ssc = (float*)(sm + 66048);
    float* ssh = ssc + 256;
    float* sb2 = ssh + 256;

    const int tid  = threadIdx.x;
    const int row0 = blockIdx.x * 128;
    ssc[tid] = g_scale[tid];
    ssh[tid] = g_shift[tid];
    if (tid < 128) sb2[tid] = b2[tid];

    const int tc = tid & 15, tr = tid >> 4;
    u64 acc[4][8];
    #pragma unroll
    for (int j = 0; j < 4; ++j)
        #pragma unroll
        for (int u = 0; u < 8; ++u) acc[j][u] = 0ull;

    for (int kc = 0; kc < HID; kc += 64) {
        __syncthreads();
        for (int idx = tid; idx < 128 * 64; idx += 256) {
            int r = idx >> 6, kk = idx & 63;
            float v = g_h[(size_t)(row0 + r) * HID + kc + kk];
            hAf[kk * 130 + r] = v * ssc[kc + kk] + ssh[kc + kk];
        }
        for (int idx = tid; idx < 64 * 128; idx += 256)
            wB[idx] = W2[(size_t)(kc + (idx >> 7)) * ENC + (idx & 127)];
        __syncthreads();

        #pragma unroll 2
        for (int kk = 0; kk < 64; ++kk) {
            u64 p0 = hA2[kk * 65 + tr * 4 + 0];
            u64 p1 = hA2[kk * 65 + tr * 4 + 1];
            u64 p2 = hA2[kk * 65 + tr * 4 + 2];
            u64 p3 = hA2[kk * 65 + tr * 4 + 3];
            float4 wa = *(const float4*)(wB + kk * 128 + tc * 8);
            float4 wb = *(const float4*)(wB + kk * 128 + tc * 8 + 4);
            float wv[8] = {wa.x, wa.y, wa.z, wa.w, wb.x, wb.y, wb.z, wb.w};
            #pragma unroll
            for (int u = 0; u < 8; ++u) {
                u64 d = dupf(wv[u]);
                fma2(acc[0][u], p0, d); fma2(acc[1][u], p1, d);
                fma2(acc[2][u], p2, d); fma2(acc[3][u], p3, d);
            }
        }
    }

    #pragma unroll
    for (int j = 0; j < 4; ++j) {
        float v0[8], v1[8];
        #pragma unroll
        for (int u = 0; u < 8; ++u) {
            float2 t = unp(acc[j][u]);
            float bb = sb2[tc * 8 + u];
            v0[u] = ftanh(t.x + bb);
            v1[u] = ftanh(t.y + bb);
        }
        int rg = row0 + tr * 8 + 2 * j;
        float* ep = g_enc + (size_t)rg * ENC + tc * 8;
        *(float4*)ep       = make_float4(v0[0], v0[1], v0[2], v0[3]);
        *(float4*)(ep + 4) = make_float4(v0[4], v0[5], v0[6], v0[7]);
        ep += ENC;
        *(float4*)ep       = make_float4(v1[0], v1[1], v1[2], v1[3]);
        *(float4*)(ep + 4) = make_float4(v1[4], v1[5], v1[6], v1[7]);
    }
}

// =====================================================================
// K4: fused distance->softmax + 10 experts + weighted output.
// smem: enc pairs [128e][65rp]u64 | eh [128][69] | We1 [128][64] |
//       We2 padded [64][12] | att [10][128] | be1/be2/attn
// =====================================================================
#define K4_SMEM (128*65*8 + 128*69*4 + 128*64*4 + (768+1280+64+16+16)*4)

__global__ void __launch_bounds__(256) k4_fused(
    const float* __restrict__ We1, const float* __restrict__ be1,
    const float* __restrict__ We2, const float* __restrict__ be2,
    const float* __restrict__ attr, float* __restrict__ out)
{
    extern __shared__ char sm[];
    u64*   enc2 = (u64*)sm;                  // e*65 + rp
    float* encf = (float*)sm;                // e*130 + r
    float* ehs  = (float*)(sm + 66560);      // [128][69]
    float* we1s = (float*)(sm + 101888);     // [128][64]
    float* we2s = (float*)(sm + 134656);     // [64][12] padded
    float* att  = we2s + 768;                // [10][128]
    float* be1s = att + 1280;                // 64
    float* be2s = be1s + 64;                 // 16
    float* attn = be2s + 16;                 // 16

    const int tid  = threadIdx.x;
    const int row0 = blockIdx.x * 128;

    for (int idx = tid; idx < 128 * 128; idx += 256) {
        int r = idx >> 7, e = idx & 127;
        encf[e * 130 + r] = g_enc[(size_t)(row0 + r) * ENC + e];
    }
    for (int idx = tid; idx < NK * ENC; idx += 256) att[idx] = attr[idx];
    __syncthreads();
    if (tid < NK) {
        float s = 0.f;
        for (int e = 0; e < ENC; ++e) { float v = att[tid * ENC + e]; s += v * v; }
        attn[tid] = s;
    }
    __syncthreads();

    // distances + softmax -> strengths in registers (threads 0..127 own a row)
    float strk[NK];
    float outacc[ACTD];
    #pragma unroll
    for (int a = 0; a < ACTD; ++a) outacc[a] = 0.f;

    if (tid < 128) {
        float en = 0.f;
        for (int e = 0; e < ENC; ++e) { float v = encf[e * 130 + tid]; en += v * v; }
        float mx = -1e30f;
        #pragma unroll
        for (int k = 0; k < NK; ++k) {
            float d = 0.f;
            for (int e = 0; e < ENC; ++e) d += encf[e * 130 + tid] * att[k * ENC + e];
            float d2 = fmaxf(en + attn[k] - 2.f * d, 0.f);
            strk[k] = -2.f * sqrtf(d2);          // -dist/TEMP, TEMP=0.5
            mx = fmaxf(mx, strk[k]);
        }
        float s = 0.f;
        #pragma unroll
        for (int k = 0; k < NK; ++k) { strk[k] = __expf(strk[k] - mx); s += strk[k]; }
        float inv = __fdividef(1.f, s);
        #pragma unroll
        for (int k = 0; k < NK; ++k) strk[k] *= inv;
    }

    const int tc = tid & 15, trr = tid >> 4;
    for (int k = 0; k < NK; ++k) {
        __syncthreads();
        for (int idx = tid; idx < ENC * EXPH; idx += 256)
            we1s[idx] = We1[(size_t)k * ENC * EXPH + idx];
        for (int idx = tid; idx < EXPH * ACTD; idx += 256)
            we2s[(idx / ACTD) * 12 + (idx % ACTD)] = We2[k * EXPH * ACTD + idx];
        if (tid < EXPH) be1s[tid] = be1[k * EXPH + tid];
        if (tid < ACTD) be2s[tid] = be2[k * ACTD + tid];
        __syncthreads();

        // phase A: eh = relu(enc @ We1_k + be1_k), 8 rows x 4 cols / thread
        u64 acc[4][4];
        #pragma unroll
        for (int j = 0; j < 4; ++j)
            #pragma unroll
            for (int u = 0; u < 4; ++u) acc[j][u] = 0ull;

        #pragma unroll 2
        for (int e = 0; e < ENC; ++e) {
            u64 p0 = enc2[e * 65 + trr * 4 + 0];
            u64 p1 = enc2[e * 65 + trr * 4 + 1];
            u64 p2 = enc2[e * 65 + trr * 4 + 2];
            u64 p3 = enc2[e * 65 + trr * 4 + 3];
            float4 w = *(const float4*)(we1s + e * 64 + tc * 4);
            float wv[4] = {w.x, w.y, w.z, w.w};
            #pragma unroll
            for (int u = 0; u < 4; ++u) {
                u64 d = dupf(wv[u]);
                fma2(acc[0][u], p0, d); fma2(acc[1][u], p1, d);
                fma2(acc[2][u], p2, d); fma2(acc[3][u], p3, d);
            }
        }
        #pragma unroll
        for (int j = 0; j < 4; ++j) {
            int r = trr * 8 + 2 * j;
            #pragma unroll
            for (int u = 0; u < 4; ++u) {
                float2 t = unp(acc[j][u]);
                float bb = be1s[tc * 4 + u];
                ehs[r * 69 + tc * 4 + u]       = fmaxf(t.x + bb, 0.f);
                ehs[(r + 1) * 69 + tc * 4 + u] = fmaxf(t.y + bb, 0.f);
            }
        }
        __syncthreads();

        // phase B: out += s_k * (eh @ We2_k + be2_k), threads 0..127 own rows
        if (tid < 128) {
            float o[ACTD];
            #pragma unroll
            for (int a = 0; a < ACTD; ++a) o[a] = 0.f;
            #pragma unroll 4
            for (int h = 0; h < EXPH; ++h) {
                float ev = ehs[tid * 69 + h];
                float4 wa = *(const float4*)(we2s + h * 12);
                float4 wb = *(const float4*)(we2s + h * 12 + 4);
                float4 wc = *(const float4*)(we2s + h * 12 + 8);
                o[0] += ev * wa.x; o[1] += ev * wa.y; o[2] += ev * wa.z; o[3] += ev * wa.w;
                o[4] += ev * wb.x; o[5] += ev * wb.y; o[6] += ev * wb.z; o[7] += ev * wb.w;
                o[8] += ev * wc.x; o[9] += ev * wc.y;
            }
            float s = strk[k];
            #pragma unroll
            for (int a = 0; a < ACTD; ++a) outacc[a] += s * (o[a] + be2s[a]);
        }
    }

    if (tid < 128) {
        float* op = out + (size_t)(row0 + tid) * ACTD;
        #pragma unroll
        for (int a = 0; a < ACTD; ++a) op[a] = outacc[a];
    }
}

// =====================================================================
extern "C" void kernel_launch(void* const* d_in, const int* in_sizes, int n_in,
                              void* d_out, int out_size)
{
    const float* state = (const float*)d_in[0];
    const float* W1    = (const float*)d_in[1];
    const float* b1    = (const float*)d_in[2];
    const float* gamma = (const float*)d_in[3];
    const float* beta  = (const float*)d_in[4];
    const float* W2    = (const float*)d_in[5];
    const float* b2    = (const float*)d_in[6];
    const float* We1   = (const float*)d_in[7];
    const float* be1   = (const float*)d_in[8];
    const float* We2   = (const float*)d_in[9];
    const float* be2   = (const float*)d_in[10];
    const float* attr  = (const float*)d_in[11];
    float* out = (float*)d_out;

    cudaFuncSetAttribute(k1_gemm_relu, cudaFuncAttributeMaxDynamicSharedMemorySize, K1_SMEM);
    cudaFuncSetAttribute(k3_gemm_tanh, cudaFuncAttributeMaxDynamicSharedMemorySize, K3_SMEM);
    cudaFuncSetAttribute(k4_fused,     cudaFuncAttributeMaxDynamicSharedMemorySize, K4_SMEM);

    k1_gemm_relu<<<dim3(GRID1, 2), 256, K1_SMEM>>>(state, W1, b1);
    k2_bnstats<<<HID, 256>>>(gamma, beta);
    k3_gemm_tanh<<<GRID1, 256, K3_SMEM>>>(W2, b2);
    k4_fused<<<GRID1, 256, K4_SMEM>>>(We1, be1, We2, be2, attr, out);
}

// round 12
// speedup vs baseline: 1.0013x; 1.0002x over previous
#include <cuda_runtime.h>

#define BATCH 262144
#define SDIM  100
#define HID   256
#define ENC   128
#define EXPH  64
#define ACTD  10
#define NK    10
#define GRID1 2048          // BATCH/128

typedef unsigned long long u64;

// ---- device-global scratch (no allocation allowed) ----
__device__ float g_h[BATCH * HID];
__device__ float g_enc[BATCH * ENC];
__device__ float g_psum[GRID1 * HID];
__device__ float g_psq [GRID1 * HID];
__device__ float g_scale[HID];
__device__ float g_shift[HID];

// ---- packed fp32x2 helpers (FFMA2 only reachable via PTX) ----
__device__ __forceinline__ u64 dupf(float w) {
    u64 d; asm("mov.b64 %0, {%1, %1};" : "=l"(d) : "f"(w)); return d;
}
__device__ __forceinline__ void fma2(u64 &a, u64 x, u64 y) {
    asm("fma.rn.f32x2 %0, %1, %2, %0;" : "+l"(a) : "l"(x), "l"(y));
}
__device__ __forceinline__ float2 unp(u64 v) {
    float2 r; asm("mov.b64 {%0, %1}, %2;" : "=f"(r.x), "=f"(r.y) : "l"(v)); return r;
}
__device__ __forceinline__ float ftanh(float x) {
    float v = fminf(fmaxf(x, -15.f), 15.f);
    float t = __expf(2.f * v);
    return __fdividef(t - 1.f, t + 1.f);
}

// =====================================================================
// K1: h = relu(state @ W1 + b1) + per-block column sum/sumsq
// grid (2048,2) x 256 thr. smem: st pairs [100][65]u64 | W1 [100][128] | b1
// =====================================================================
#define K1_SMEM (100*65*8 + 100*128*4 + 128*4)   // 52000+51200+512 = 103712

__global__ void __launch_bounds__(256) k1_gemm_relu(
    const float* __restrict__ state, const float* __restrict__ W1,
    const float* __restrict__ b1)
{
    extern __shared__ char sm[];
    float* stf = (float*)sm;                 // float view: k*130 + r
    u64*   st2 = (u64*)sm;                   // pair view:  k*65 + rp
    float* w1s = (float*)(sm + 52000);       // [100][128]
    float* b1s = (float*)(sm + 103200);

    const int tid  = threadIdx.x;
    const int row0 = blockIdx.x * 128;
    const int cb   = blockIdx.y;

    for (int idx = tid; idx < 128 * SDIM; idx += 256) {
        int r = idx / SDIM, k = idx - r * SDIM;
        stf[k * 130 + r] = state[(size_t)(row0 + r) * SDIM + k];
    }
    for (int idx = tid; idx < SDIM * 128; idx += 256) {
        int k = idx >> 7, c = idx & 127;
        w1s[idx] = W1[k * HID + cb * 128 + c];
    }
    if (tid < 128) b1s[tid] = b1[cb * 128 + tid];
    __syncthreads();

    const int tc = tid & 15, tr = tid >> 4;
    u64 acc[4][8];
    #pragma unroll
    for (int j = 0; j < 4; ++j)
        #pragma unroll
        for (int u = 0; u < 8; ++u) acc[j][u] = 0ull;

    #pragma unroll 2
    for (int k = 0; k < SDIM; ++k) {
        u64 p0 = st2[k * 65 + tr * 4 + 0];
        u64 p1 = st2[k * 65 + tr * 4 + 1];
        u64 p2 = st2[k * 65 + tr * 4 + 2];
        u64 p3 = st2[k * 65 + tr * 4 + 3];
        float4 wa = *(const float4*)(w1s + k * 128 + tc * 8);
        float4 wb = *(const float4*)(w1s + k * 128 + tc * 8 + 4);
        float wv[8] = {wa.x, wa.y, wa.z, wa.w, wb.x, wb.y, wb.z, wb.w};
        #pragma unroll
        for (int u = 0; u < 8; ++u) {
            u64 d = dupf(wv[u]);
            fma2(acc[0][u], p0, d); fma2(acc[1][u], p1, d);
            fma2(acc[2][u], p2, d); fma2(acc[3][u], p3, d);
        }
    }

    float csum[8], csq[8], bvals[8];
    #pragma unroll
    for (int u = 0; u < 8; ++u) { csum[u] = 0.f; csq[u] = 0.f; bvals[u] = b1s[tc * 8 + u]; }

    #pragma unroll
    for (int j = 0; j < 4; ++j) {
        float v0[8], v1[8];
        #pragma unroll
        for (int u = 0; u < 8; ++u) {
            float2 t = unp(acc[j][u]);
            float x0 = fmaxf(t.x + bvals[u], 0.f);
            float x1 = fmaxf(t.y + bvals[u], 0.f);
            v0[u] = x0; v1[u] = x1;
            csum[u] += x0 + x1;
            csq[u]  += x0 * x0 + x1 * x1;
        }
        int rg = row0 + tr * 8 + 2 * j;
        float* hp = g_h + (size_t)rg * HID + cb * 128 + tc * 8;
        *(float4*)hp       = make_float4(v0[0], v0[1], v0[2], v0[3]);
        *(float4*)(hp + 4) = make_float4(v0[4], v0[5], v0[6], v0[7]);
        hp += HID;
        *(float4*)hp       = make_float4(v1[0], v1[1], v1[2], v1[3]);
        *(float4*)(hp + 4) = make_float4(v1[4], v1[5], v1[6], v1[7]);
    }

    __syncthreads();
    float* red = (float*)sm;                 // alias, [16][128]
    #pragma unroll
    for (int u = 0; u < 8; ++u) red[tr * 128 + tc * 8 + u] = csum[u];
    __syncthreads();
    if (tid < 128) {
        float s = 0.f;
        #pragma unroll
        for (int q = 0; q < 16; ++q) s += red[q * 128 + tid];
        g_psum[blockIdx.x * HID + cb * 128 + tid] = s;
    }
    __syncthreads();
    #pragma unroll
    for (int u = 0; u < 8; ++u) red[tr * 128 + tc * 8 + u] = csq[u];
    __syncthreads();
    if (tid < 128) {
        float s = 0.f;
        #pragma unroll
        for (int q = 0; q < 16; ++q) s += red[q * 128 + tid];
        g_psq[blockIdx.x * HID + cb * 128 + tid] = s;
    }
}

// =====================================================================
// K2: finalize BN stats -> scale/shift
// =====================================================================
__global__ void k2_bnstats(const float* __restrict__ gamma,
                           const float* __restrict__ beta)
{
    __shared__ float rs[256], rq[256];
    const int c = blockIdx.x, tid = threadIdx.x;
    float s = 0.f, q = 0.f;
    for (int i = tid; i < GRID1; i += 256) {
        s += g_psum[i * HID + c];
        q += g_psq [i * HID + c];
    }
    rs[tid] = s; rq[tid] = q;
    __syncthreads();
    for (int off = 128; off > 0; off >>= 1) {
        if (tid < off) { rs[tid] += rs[tid + off]; rq[tid] += rq[tid + off]; }
        __syncthreads();
    }
    if (tid == 0) {
        const float invB = 1.f / (float)BATCH;
        float mu  = rs[0] * invB;
        float var = fmaxf(rq[0] * invB - mu * mu, 0.f);
        float sc  = gamma[c] * rsqrtf(var + 1e-5f);
        g_scale[c] = sc;
        g_shift[c] = beta[c] - mu * sc;
    }
}

// =====================================================================
// K3: enc = tanh( BN(h) @ W2 + b2 ). 128x128 tile, K=256 in chunks of 64.
// smem: A pairs [64][65]u64 | W2 chunk [64][128] | scale/shift/b2
// =====================================================================
#define K3_SMEM (64*65*8 + 64*128*4 + 256*4*2 + 128*4)  // 33280+32768+2048+512

__global__ void __launch_bounds__(256) k3_gemm_tanh(
    const float* __restrict__ W2, const float* __restrict__ b2)
{
    extern __shared__ char sm[];
    u64*   hA2 = (u64*)sm;                   // [kk][65]
    float* hAf = (float*)sm;                 // kk*130 + r
    float* wB  = (float*)(sm + 33280);       // [64][128]
    float* ssc = (float*)(sm + 66048);
    float* ssh = ssc + 256;
    float* sb2 = ssh + 256;

    const int tid  = threadIdx.x;
    const int row0 = blockIdx.x * 128;
    ssc[tid] = g_scale[tid];
    ssh[tid] = g_shift[tid];
    if (tid < 128) sb2[tid] = b2[tid];

    const int tc = tid & 15, tr = tid >> 4;
    u64 acc[4][8];
    #pragma unroll
    for (int j = 0; j < 4; ++j)
        #pragma unroll
        for (int u = 0; u < 8; ++u) acc[j][u] = 0ull;

    for (int kc = 0; kc < HID; kc += 64) {
        __syncthreads();
        for (int idx = tid; idx < 128 * 64; idx += 256) {
            int r = idx >> 6, kk = idx & 63;
            float v = g_h[(size_t)(row0 + r) * HID + kc + kk];
            hAf[kk * 130 + r] = v * ssc[kc + kk] + ssh[kc + kk];
        }
        for (int idx = tid; idx < 64 * 128; idx += 256)
            wB[idx] = W2[(size_t)(kc + (idx >> 7)) * ENC + (idx & 127)];
        __syncthreads();

        #pragma unroll 2
        for (int kk = 0; kk < 64; ++kk) {
            u64 p0 = hA2[kk * 65 + tr * 4 + 0];
            u64 p1 = hA2[kk * 65 + tr * 4 + 1];
            u64 p2 = hA2[kk * 65 + tr * 4 + 2];
            u64 p3 = hA2[kk * 65 + tr * 4 + 3];
            float4 wa = *(const float4*)(wB + kk * 128 + tc * 8);
            float4 wb = *(const float4*)(wB + kk * 128 + tc * 8 + 4);
            float wv[8] = {wa.x, wa.y, wa.z, wa.w, wb.x, wb.y, wb.z, wb.w};
            #pragma unroll
            for (int u = 0; u < 8; ++u) {
                u64 d = dupf(wv[u]);
                fma2(acc[0][u], p0, d); fma2(acc[1][u], p1, d);
                fma2(acc[2][u], p2, d); fma2(acc[3][u], p3, d);
            }
        }
    }

    #pragma unroll
    for (int j = 0; j < 4; ++j) {
        float v0[8], v1[8];
        #pragma unroll
        for (int u = 0; u < 8; ++u) {
            float2 t = unp(acc[j][u]);
            float bb = sb2[tc * 8 + u];
            v0[u] = ftanh(t.x + bb);
            v1[u] = ftanh(t.y + bb);
        }
        int rg = row0 + tr * 8 + 2 * j;
        float* ep = g_enc + (size_t)rg * ENC + tc * 8;
        *(float4*)ep       = make_float4(v0[0], v0[1], v0[2], v0[3]);
        *(float4*)(ep + 4) = make_float4(v0[4], v0[5], v0[6], v0[7]);
        ep += ENC;
        *(float4*)ep       = make_float4(v1[0], v1[1], v1[2], v1[3]);
        *(float4*)(ep + 4) = make_float4(v1[4], v1[5], v1[6], v1[7]);
    }
}

// =====================================================================
// K4: fused distance->softmax + 10 experts + weighted output.
// smem: enc pairs [128e][65rp]u64 | eh [128][69] | We1 [128][64] |
//       We2 padded [64][12] | att [10][128] | be1/be2/attn
// =====================================================================
#define K4_SMEM (128*65*8 + 128*69*4 + 128*64*4 + (768+1280+64+16+16)*4)

__global__ void __launch_bounds__(256) k4_fused(
    const float* __restrict__ We1, const float* __restrict__ be1,
    const float* __restrict__ We2, const float* __restrict__ be2,
    const float* __restrict__ attr, float* __restrict__ out)
{
    extern __shared__ char sm[];
    u64*   enc2 = (u64*)sm;                  // e*65 + rp
    float* encf = (float*)sm;                // e*130 + r
    float* ehs  = (float*)(sm + 66560);      // [128][69]
    float* we1s = (float*)(sm + 101888);     // [128][64]
    float* we2s = (float*)(sm + 134656);     // [64][12] padded
    float* att  = we2s + 768;                // [10][128]
    float* be1s = att + 1280;                // 64
    float* be2s = be1s + 64;                 // 16
    float* attn = be2s + 16;                 // 16

    const int tid  = threadIdx.x;
    const int row0 = blockIdx.x * 128;

    for (int idx = tid; idx < 128 * 128; idx += 256) {
        int r = idx >> 7, e = idx & 127;
        encf[e * 130 + r] = g_enc[(size_t)(row0 + r) * ENC + e];
    }
    for (int idx = tid; idx < NK * ENC; idx += 256) att[idx] = attr[idx];
    __syncthreads();
    if (tid < NK) {
        float s = 0.f;
        for (int e = 0; e < ENC; ++e) { float v = att[tid * ENC + e]; s += v * v; }
        attn[tid] = s;
    }
    __syncthreads();

    // distances + softmax -> strengths in registers (threads 0..127 own a row)
    float strk[NK];
    float outacc[ACTD];
    #pragma unroll
    for (int a = 0; a < ACTD; ++a) outacc[a] = 0.f;

    if (tid < 128) {
        float en = 0.f;
        for (int e = 0; e < ENC; ++e) { float v = encf[e * 130 + tid]; en += v * v; }
        float mx = -1e30f;
        #pragma unroll
        for (int k = 0; k < NK; ++k) {
            float d = 0.f;
            for (int e = 0; e < ENC; ++e) d += encf[e * 130 + tid] * att[k * ENC + e];
            float d2 = fmaxf(en + attn[k] - 2.f * d, 0.f);
            strk[k] = -2.f * sqrtf(d2);          // -dist/TEMP, TEMP=0.5
            mx = fmaxf(mx, strk[k]);
        }
        float s = 0.f;
        #pragma unroll
        for (int k = 0; k < NK; ++k) { strk[k] = __expf(strk[k] - mx); s += strk[k]; }
        float inv = __fdividef(1.f, s);
        #pragma unroll
        for (int k = 0; k < NK; ++k) strk[k] *= inv;
    }

    const int tc = tid & 15, trr = tid >> 4;
    for (int k = 0; k < NK; ++k) {
        __syncthreads();
        for (int idx = tid; idx < ENC * EXPH; idx += 256)
            we1s[idx] = We1[(size_t)k * ENC * EXPH + idx];
        for (int idx = tid; idx < EXPH * ACTD; idx += 256)
            we2s[(idx / ACTD) * 12 + (idx % ACTD)] = We2[k * EXPH * ACTD + idx];
        if (tid < EXPH) be1s[tid] = be1[k * EXPH + tid];
        if (tid < ACTD) be2s[tid] = be2[k * ACTD + tid];
        __syncthreads();

        // phase A: eh = relu(enc @ We1_k + be1_k), 8 rows x 4 cols / thread
        u64 acc[4][4];
        #pragma unroll
        for (int j = 0; j < 4; ++j)
            #pragma unroll
            for (int u = 0; u < 4; ++u) acc[j][u] = 0ull;

        #pragma unroll 2
        for (int e = 0; e < ENC; ++e) {
            u64 p0 = enc2[e * 65 + trr * 4 + 0];
            u64 p1 = enc2[e * 65 + trr * 4 + 1];
            u64 p2 = enc2[e * 65 + trr * 4 + 2];
            u64 p3 = enc2[e * 65 + trr * 4 + 3];
            float4 w = *(const float4*)(we1s + e * 64 + tc * 4);
            float wv[4] = {w.x, w.y, w.z, w.w};
            #pragma unroll
            for (int u = 0; u < 4; ++u) {
                u64 d = dupf(wv[u]);
                fma2(acc[0][u], p0, d); fma2(acc[1][u], p1, d);
                fma2(acc[2][u], p2, d); fma2(acc[3][u], p3, d);
            }
        }
        #pragma unroll
        for (int j = 0; j < 4; ++j) {
            int r = trr * 8 + 2 * j;
            #pragma unroll
            for (int u = 0; u < 4; ++u) {
                float2 t = unp(acc[j][u]);
                float bb = be1s[tc * 4 + u];
                ehs[r * 69 + tc * 4 + u]       = fmaxf(t.x + bb, 0.f);
                ehs[(r + 1) * 69 + tc * 4 + u] = fmaxf(t.y + bb, 0.f);
            }
        }
        __syncthreads();

        // phase B: out += s_k * (eh @ We2_k + be2_k), threads 0..127 own rows
        if (tid < 128) {
            float o[ACTD];
            #pragma unroll
            for (int a = 0; a < ACTD; ++a) o[a] = 0.f;
            #pragma unroll 4
            for (int h = 0; h < EXPH; ++h) {
                float ev = ehs[tid * 69 + h];
                float4 wa = *(const float4*)(we2s + h * 12);
                float4 wb = *(const float4*)(we2s + h * 12 + 4);
                float4 wc = *(const float4*)(we2s + h * 12 + 8);
                o[0] += ev * wa.x; o[1] += ev * wa.y; o[2] += ev * wa.z; o[3] += ev * wa.w;
                o[4] += ev * wb.x; o[5] += ev * wb.y; o[6] += ev * wb.z; o[7] += ev * wb.w;
                o[8] += ev * wc.x; o[9] += ev * wc.y;
            }
            float s = strk[k];
            #pragma unroll
            for (int a = 0; a < ACTD; ++a) outacc[a] += s * (o[a] + be2s[a]);
        }
    }

    if (tid < 128) {
        float* op = out + (size_t)(row0 + tid) * ACTD;
        #pragma unroll
        for (int a = 0; a < ACTD; ++a) op[a] = outacc[a];
    }
}

// =====================================================================
extern "C" void kernel_launch(void* const* d_in, const int* in_sizes, int n_in,
                              void* d_out, int out_size)
{
    const float* state = (const float*)d_in[0];
    const float* W1    = (const float*)d_in[1];
    const float* b1    = (const float*)d_in[2];
    const float* gamma = (const float*)d_in[3];
    const float* beta  = (const float*)d_in[4];
    const float* W2    = (const float*)d_in[5];
    const float* b2    = (const float*)d_in[6];
    const float* We1   = (const float*)d_in[7];
    const float* be1   = (const float*)d_in[8];
    const float* We2   = (const float*)d_in[9];
    const float* be2   = (const float*)d_in[10];
    const float* attr  = (const float*)d_in[11];
    float* out = (float*)d_out;

    cudaFuncSetAttribute(k1_gemm_relu, cudaFuncAttributeMaxDynamicSharedMemorySize, K1_SMEM);
    cudaFuncSetAttribute(k3_gemm_tanh, cudaFuncAttributeMaxDynamicSharedMemorySize, K3_SMEM);
    cudaFuncSetAttribute(k4_fused,     cudaFuncAttributeMaxDynamicSharedMemorySize, K4_SMEM);

    k1_gemm_relu<<<dim3(GRID1, 2), 256, K1_SMEM>>>(state, W1, b1);
    k2_bnstats<<<HID, 256>>>(gamma, beta);
    k3_gemm_tanh<<<GRID1, 256, K3_SMEM>>>(W2, b2);
    k4_fused<<<GRID1, 256, K4_SMEM>>>(We1, be1, We2, be2, attr, out);
}